// round 7
// baseline (speedup 1.0000x reference)
#include <cuda_runtime.h>

// out[b,o] = min_i max(x[b,i], w[i,o])   (forward of STE expr == hard min-max)
//
// SINGLE fused kernel, one block per batch row b, all fp32 (rel_err = 0):
//   1. 256-bin counting sort of x[b,:] by value, entirely in smem.
//   2. Warp-pruned scan: candidates in increasing-x order; a warp (128
//      contiguous o's, 4 per lane) exits when bin_floor(next x) >= max of its
//      lanes' bests -- every remaining candidate i has x_i >= bound >= best,
//      so max(x_i, w) >= best. Exact result, independent of within-bin order.
//   Exit branch is warp-uniform so the unrolled gather body stays
//   unpredicated -> LDGs front-batched (R4 lesson: lane predication kills MLP).
//
// Fusing removes the g_xsort gmem round-trip, the w->fp16 convert kernel,
// and one launch+dependency gap (4.3us of R6's 14.4us total).

#define DB 512
#define DI 512
#define DO 1024
#define NBIN 256

__global__ __launch_bounds__(256) void k_fused(const float* __restrict__ x,
                                               const float* __restrict__ w,
                                               float* __restrict__ out) {
    __shared__ uint2 sx[DI];      // bin-ordered {fp32 bits of x, idx}, 4 KB
    __shared__ int hist[NBIN];
    __shared__ int offs[NBIN];
    __shared__ int wsum[8];

    const int b = blockIdx.x;
    const int tid = threadIdx.x;
    const int lane = tid & 31, wid = tid >> 5;

    // ---- phase 1: counting sort of x[b,:] by value (smem only) ----
    hist[tid] = 0;
    __syncthreads();

    float v0 = x[b * DI + tid];
    float v1 = x[b * DI + tid + 256];
    int bin0 = min(NBIN - 1, (int)(v0 * (float)NBIN));
    int bin1 = min(NBIN - 1, (int)(v1 * (float)NBIN));
    atomicAdd(&hist[bin0], 1);
    atomicAdd(&hist[bin1], 1);
    __syncthreads();

    // exclusive prefix over 256 bins (thread t owns bin t)
    int pv = hist[tid];
#pragma unroll
    for (int off = 1; off < 32; off <<= 1) {
        int n = __shfl_up_sync(0xffffffffu, pv, off);
        if (lane >= off) pv += n;
    }
    if (lane == 31) wsum[wid] = pv;
    __syncthreads();
    if (tid < 8) {
        int s = wsum[tid];
#pragma unroll
        for (int off = 1; off < 8; off <<= 1) {
            int n = __shfl_up_sync(0xffu, s, off);
            if (tid >= off) s += n;
        }
        wsum[tid] = s;
    }
    __syncthreads();
    offs[tid] = pv + (wid ? wsum[wid - 1] : 0) - hist[tid];
    __syncthreads();

    {
        int p0 = atomicAdd(&offs[bin0], 1);
        sx[p0] = make_uint2(__float_as_uint(v0), (unsigned)tid);
        int p1 = atomicAdd(&offs[bin1], 1);
        sx[p1] = make_uint2(__float_as_uint(v1), (unsigned)(tid + 256));
    }
    __syncthreads();

    // ---- phase 2: pruned scan (warp-uniform exit, unpredicated body) ----
    const float finf = __int_as_float(0x7f800000);
    float a0 = finf, a1 = finf, a2 = finf, a3 = finf;
    // this thread owns o = wid*128 + lane*4 .. +3 ; warp owns 128 contiguous o
    const float* wb = w + wid * 128 + lane * 4;

    for (int k = 0; k < DI; k += 16) {
        if (k) {
            // lower bound for every candidate at position >= k: same-or-later
            // bin, so value >= bin_floor(value at position k).
            float nv = __uint_as_float(sx[k].x);
            int nbin = min(NBIN - 1, (int)(nv * (float)NBIN));
            float bound = (float)nbin * (1.0f / (float)NBIN);
            float m = fmaxf(fmaxf(a0, a1), fmaxf(a2, a3));
            if (__all_sync(0xffffffffu, bound >= m)) break;
        }
#pragma unroll
        for (int kk = 0; kk < 16; kk++) {
            uint2 e = sx[k + kk];
            float xv = __uint_as_float(e.x);
            const float4 wv = *reinterpret_cast<const float4*>(wb + e.y * DO);
            a0 = fminf(a0, fmaxf(xv, wv.x));
            a1 = fminf(a1, fmaxf(xv, wv.y));
            a2 = fminf(a2, fmaxf(xv, wv.z));
            a3 = fminf(a3, fmaxf(xv, wv.w));
        }
    }

    float4 r = make_float4(a0, a1, a2, a3);
    *reinterpret_cast<float4*>(&out[b * DO + wid * 128 + lane * 4]) = r;
}

extern "C" void kernel_launch(void* const* d_in, const int* in_sizes, int n_in,
                              void* d_out, int out_size) {
    const float* x = (const float*)d_in[0];   // [512, 512]
    const float* w = (const float*)d_in[1];   // [512, 1024]
    float* out = (float*)d_out;               // [512, 1024]

    k_fused<<<DB, 256>>>(x, w, out);          // one block per batch row
}

// round 8
// speedup vs baseline: 1.1482x; 1.1482x over previous
#include <cuda_runtime.h>
#include <cuda_fp16.h>

// out[b,o] = min_i max(x[b,i], w[i,o])   (forward of STE expr == hard min-max)
//
// R7 post-mortem: the gather loop is L1tex WAVEFRONT-bound (sectors/SM/cyc).
// fp32 w = 16 sectors per warp-candidate; fp16 = 8. So: tiny convert kernel
// (w -> fp16 once, ~3MB traffic) + fused sort+scan with fp16 gathers.
//
// Fused kernel, one block per row b:
//   1. 256-bin counting sort of x[b,:] by (half-rounded) value, smem only.
//   2. Warp-pruned scan: candidates in increasing-x order; a warp (128
//      contiguous o's, 4 per lane) exits when bin_floor(next x) >= max of its
//      lanes' bests -- remaining candidates have x_i >= bound >= best, so
//      max(x_i, w) >= best. Exact in the fp16 domain, order-independent.
//   Exit branch is warp-uniform -> gather body unpredicated -> LDGs batched
//   (R4 lesson: per-lane predication collapses MLP).
//
// fp16 RN rounding bounds rel err by ~2^-11 < 1e-3.

#define DB 512
#define DI 512
#define DO 1024
#define NBIN 256

__device__ __half g_wh[DI * DO];   // fp16 w, 1 MB

// ---------- Kernel 1: w fp32 -> fp16, 128 blocks, MLP=4 ----------
__global__ __launch_bounds__(256) void k_convert(const float* __restrict__ w) {
    const int tid = threadIdx.x;
    const int c = blockIdx.x;
    float4 v[4];
#pragma unroll
    for (int e = 0; e < 4; e++)
        v[e] = reinterpret_cast<const float4*>(w)[c * 1024 + e * 256 + tid];
#pragma unroll
    for (int e = 0; e < 4; e++) {
        __half2 h0 = __floats2half2_rn(v[e].x, v[e].y);
        __half2 h1 = __floats2half2_rn(v[e].z, v[e].w);
        reinterpret_cast<uint2*>(g_wh)[c * 1024 + e * 256 + tid] =
            make_uint2(*reinterpret_cast<unsigned*>(&h0),
                       *reinterpret_cast<unsigned*>(&h1));
    }
}

// ---------- Kernel 2: fused sort + pruned scan ----------
__global__ __launch_bounds__(256) void k_fused(const float* __restrict__ x,
                                               float* __restrict__ out) {
    __shared__ uint2 sx[DI];      // bin-ordered {dup-half2(x), idx}, 4 KB
    __shared__ int hist[NBIN];
    __shared__ int offs[NBIN];
    __shared__ int wsum[8];

    const int b = blockIdx.x;
    const int tid = threadIdx.x;
    const int lane = tid & 31, wid = tid >> 5;

    // ---- phase 1: counting sort of x[b,:] by half-rounded value ----
    hist[tid] = 0;
    __syncthreads();

    __half h0 = __float2half_rn(x[b * DI + tid]);
    __half h1 = __float2half_rn(x[b * DI + tid + 256]);
    int bin0 = min(NBIN - 1, (int)(__half2float(h0) * (float)NBIN));
    int bin1 = min(NBIN - 1, (int)(__half2float(h1) * (float)NBIN));
    atomicAdd(&hist[bin0], 1);
    atomicAdd(&hist[bin1], 1);
    __syncthreads();

    // exclusive prefix over 256 bins (thread t owns bin t)
    int pv = hist[tid];
#pragma unroll
    for (int off = 1; off < 32; off <<= 1) {
        int n = __shfl_up_sync(0xffffffffu, pv, off);
        if (lane >= off) pv += n;
    }
    if (lane == 31) wsum[wid] = pv;
    __syncthreads();
    if (tid < 8) {
        int s = wsum[tid];
#pragma unroll
        for (int off = 1; off < 8; off <<= 1) {
            int n = __shfl_up_sync(0xffu, s, off);
            if (tid >= off) s += n;
        }
        wsum[tid] = s;
    }
    __syncthreads();
    offs[tid] = pv + (wid ? wsum[wid - 1] : 0) - hist[tid];
    __syncthreads();

    {
        unsigned u0 = (unsigned)__half_as_ushort(h0);
        unsigned u1 = (unsigned)__half_as_ushort(h1);
        int p0 = atomicAdd(&offs[bin0], 1);
        sx[p0] = make_uint2(u0 | (u0 << 16), (unsigned)tid);
        int p1 = atomicAdd(&offs[bin1], 1);
        sx[p1] = make_uint2(u1 | (u1 << 16), (unsigned)(tid + 256));
    }
    __syncthreads();

    // ---- phase 2: pruned fp16 scan (warp-uniform exit, unpredicated body) ----
    const unsigned infu = 0x7C007C00u;   // {+inf,+inf} fp16
    __half2 best0 = *reinterpret_cast<const __half2*>(&infu);
    __half2 best1 = best0;

    // this thread owns o = wid*128 + lane*4 .. +3 ; warp owns 128 contiguous o
    const __half* wb = g_wh + wid * 128 + lane * 4;

    for (int k = 0; k < DI; k += 16) {
        if (k) {
            // lower bound for all candidates at position >= k: same-or-later
            // bin, so value >= bin_floor(value at position k).
            unsigned nx = sx[k].x & 0xFFFFu;
            float nv = __half2float(__ushort_as_half((unsigned short)nx));
            int nbin = min(NBIN - 1, (int)(nv * (float)NBIN));
            float bound = (float)nbin * (1.0f / (float)NBIN);
            __half2 m2 = __hmax2(best0, best1);
            float m = fmaxf(__low2float(m2), __high2float(m2));
            if (__all_sync(0xffffffffu, bound >= m)) break;
        }
#pragma unroll
        for (int kk = 0; kk < 16; kk++) {
            uint2 e = sx[k + kk];
            __half2 xv = *reinterpret_cast<__half2*>(&e.x);
            uint2 wv = *reinterpret_cast<const uint2*>(wb + (e.y << 10));
            best0 = __hmin2(best0, __hmax2(xv, *reinterpret_cast<__half2*>(&wv.x)));
            best1 = __hmin2(best1, __hmax2(xv, *reinterpret_cast<__half2*>(&wv.y)));
        }
    }

    float4 r;
    r.x = __low2float(best0);  r.y = __high2float(best0);
    r.z = __low2float(best1);  r.w = __high2float(best1);
    *reinterpret_cast<float4*>(&out[b * DO + wid * 128 + lane * 4]) = r;
}

extern "C" void kernel_launch(void* const* d_in, const int* in_sizes, int n_in,
                              void* d_out, int out_size) {
    const float* x = (const float*)d_in[0];   // [512, 512]
    const float* w = (const float*)d_in[1];   // [512, 1024]
    float* out = (float*)d_out;               // [512, 1024]

    k_convert<<<128, 256>>>(w);       // w -> fp16 (1 MB), ~1 us
    k_fused<<<DB, 256>>>(x, out);     // one block per batch row
}